// round 5
// baseline (speedup 1.0000x reference)
#include <cuda_runtime.h>
#include <math.h>

constexpr int cB = 64, cT = 256, cE = 128, cDEG = 8, cHID = 100;
constexpr int cTM1 = 255, cNBUCKET = 288;

// ---------------- device scratch ----------------
__device__ float g_X [cB*cT*cE];
__device__ float g_Q [cB*cT*cE];
__device__ float g_K [cB*cT*cE];
__device__ float g_V [cB*cT*cE];
__device__ float g_AH[cB*cT*cE];
__device__ float g_Hc[cB*cT*cHID];
__device__ float g_WoW1[cE*cHID];
__device__ float g_Db[cB*cHID];
__device__ float g_Ad[cHID], g_Ax[cHID], g_Ay[cHID], g_Cv[cHID];
__device__ float g_u1[25], g_w1b[25];
__device__ float g_stats[3];
__device__ float g_white[2];
__device__ float g_per[cB];

// ---------------- init ----------------
__global__ void init_kernel() {
    int t = threadIdx.x;
    if (t < cB) g_per[t] = 0.f;
    if (t < 3)  g_stats[t] = 0.f;
}

// ---------------- embedding gather (float4) ----------------
__global__ void gather_kernel(const int* __restrict__ xs, const float* __restrict__ emb) {
    int tid = threadIdx.x;
    int row = blockIdx.x*8 + (tid >> 5);
    int e4 = (tid & 31) << 2;
    float4 v = *(const float4*)(emb + (long)xs[row]*cE + e4);
    *(float4*)(g_X + (long)row*cE + e4) = v;
}

// ================= 128x128x128 GEMM, 8x8 register tiles =================
// C = A[16384,128] @ B[128,N].  blockIdx.x selects (B,C) pair (QKV fusion).
// skipmode 1: skip M-tile if t0 >= ceil64(len); skipmode 2: skip if t0 >= len-1.
__global__ __launch_bounds__(256)
void gemm128(const float* __restrict__ A,
             const float* __restrict__ B0, const float* __restrict__ B1,
             const float* __restrict__ B2,
             float* __restrict__ C0, float* __restrict__ C1, float* __restrict__ C2,
             const int* __restrict__ lengths, int N, int skipmode) {
    int m0 = blockIdx.y * 128;
    int b  = m0 >> 8, t0 = m0 & 255;
    int len = lengths[b];
    if (skipmode == 1 && t0 >= ((len + 63) & ~63)) return;
    if (skipmode == 2 && t0 >= len - 1) return;
    const float* Bm = (blockIdx.x == 0) ? B0 : (blockIdx.x == 1 ? B1 : B2);
    float*       C  = (blockIdx.x == 0) ? C0 : (blockIdx.x == 1 ? C1 : C2);

    __shared__ float As[128*17];
    __shared__ float Bs[16*128];
    int tid = threadIdx.x;
    int tx = tid & 15, ty = tid >> 4;
    float acc[8][8] = {};

    for (int k0 = 0; k0 < 128; k0 += 16) {
        {   // A tile [128][16] -> As (pad 17)
            int r = tid >> 1, c = (tid & 1) * 8;
            const float* ap = A + (long)(m0 + r)*cE + k0 + c;
            float4 v0 = *(const float4*)ap;
            float4 v1 = *(const float4*)(ap + 4);
            float* as = As + r*17 + c;
            as[0]=v0.x; as[1]=v0.y; as[2]=v0.z; as[3]=v0.w;
            as[4]=v1.x; as[5]=v1.y; as[6]=v1.z; as[7]=v1.w;
        }
        {   // B tile [16][N<=128] -> Bs (stride 128)
            int r = tid >> 4, c = (tid & 15) * 8;
            float4 z = make_float4(0.f,0.f,0.f,0.f);
            const float* bp = Bm + (long)(k0 + r)*N + c;
            float4 v0 = (c     < N) ? *(const float4*)bp       : z;
            float4 v1 = (c + 4 < N) ? *(const float4*)(bp + 4) : z;
            *(float4*)(Bs + r*128 + c)     = v0;
            *(float4*)(Bs + r*128 + c + 4) = v1;
        }
        __syncthreads();
        #pragma unroll
        for (int kk = 0; kk < 16; kk++) {
            float a[8];
            #pragma unroll
            for (int i = 0; i < 4; i++) {
                a[i]   = As[(ty*4 + i)*17 + kk];
                a[4+i] = As[(64 + ty*4 + i)*17 + kk];
            }
            float4 b0 = *(float4*)(Bs + kk*128 + tx*4);
            float4 b1 = *(float4*)(Bs + kk*128 + 64 + tx*4);
            float bb[8] = {b0.x,b0.y,b0.z,b0.w,b1.x,b1.y,b1.z,b1.w};
            #pragma unroll
            for (int i = 0; i < 8; i++)
                #pragma unroll
                for (int j = 0; j < 8; j++)
                    acc[i][j] += a[i]*bb[j];
        }
        __syncthreads();
    }
    // store C
    #pragma unroll
    for (int i = 0; i < 8; i++) {
        int row = m0 + ((i < 4) ? (ty*4 + i) : (64 + ty*4 + i - 4));
        float* cp = C + (long)row*N;
        int c0 = tx*4, c1 = 64 + tx*4;
        float4 o0 = make_float4(acc[i][0],acc[i][1],acc[i][2],acc[i][3]);
        float4 o1 = make_float4(acc[i][4],acc[i][5],acc[i][6],acc[i][7]);
        if (c0 < N) *(float4*)(cp + c0) = o0;
        if (c1 < N) *(float4*)(cp + c1) = o1;
    }
}

// ================= fused flash attention =================
// grid (4, 64): q-tile (reversed for balance), batch. 256 threads.
__global__ __launch_bounds__(256)
void attn_kernel(const int* __restrict__ lengths) {
    extern __shared__ float sm[];
    float* Qs = sm;               // [64][129]
    float* KVs = sm + 64*129;     // K: stride 129; V: stride 128 (reused)
    float* Ps = sm + 2*64*129;    // [64][65]

    int b  = blockIdx.y;
    int qt = 3 - blockIdx.x;
    int q0 = qt * 64;
    int len = lengths[b];
    if (q0 >= len) return;

    int tid = threadIdx.x;
    int tx = tid & 15, ty = tid >> 4;
    const float scale = 0.08838834764831845f;

    // load Q (scaled) into Qs
    const float* Qg = g_Q + (long)(b*cT + q0)*cE;
    #pragma unroll
    for (int i = 0; i < 8; i++) {
        int idx = tid + i*256;
        int r = idx >> 5, e4 = (idx & 31) << 2;
        float4 v = *(const float4*)(Qg + r*cE + e4);
        float* qs = Qs + r*129 + e4;
        qs[0]=v.x*scale; qs[1]=v.y*scale; qs[2]=v.z*scale; qs[3]=v.w*scale;
    }
    float O[4][8] = {};
    float mr[4], lr[4];
    #pragma unroll
    for (int i = 0; i < 4; i++) { mr[i] = -1e30f; lr[i] = 0.f; }
    __syncthreads();

    int ktmax = min(qt, ((len + 63) >> 6) - 1);
    for (int kt = 0; kt <= ktmax; kt++) {
        // ---- load K tile (stride 129) ----
        const float* Kg = g_K + (long)(b*cT + kt*64)*cE;
        #pragma unroll
        for (int i = 0; i < 8; i++) {
            int idx = tid + i*256;
            int r = idx >> 5, e4 = (idx & 31) << 2;
            float4 v = *(const float4*)(Kg + r*cE + e4);
            float* ks = KVs + r*129 + e4;
            ks[0]=v.x; ks[1]=v.y; ks[2]=v.z; ks[3]=v.w;
        }
        __syncthreads();
        // ---- S = Q K^T ----
        float s[4][4] = {};
        #pragma unroll 4
        for (int kk = 0; kk < 128; kk++) {
            float a[4], bb[4];
            #pragma unroll
            for (int i = 0; i < 4; i++) a[i]  = Qs[(ty*4 + i)*129 + kk];
            #pragma unroll
            for (int j = 0; j < 4; j++) bb[j] = KVs[(tx*4 + j)*129 + kk];
            #pragma unroll
            for (int i = 0; i < 4; i++)
                #pragma unroll
                for (int j = 0; j < 4; j++)
                    s[i][j] += a[i]*bb[j];
        }
        // ---- mask ----
        int kbase = kt*64;
        bool diag = (kt == qt);
        #pragma unroll
        for (int i = 0; i < 4; i++) {
            int q = q0 + ty*4 + i;
            #pragma unroll
            for (int j = 0; j < 4; j++) {
                int k = kbase + tx*4 + j;
                if ((diag && k > q) || k >= len) s[i][j] = -1e30f;
            }
        }
        // ---- online softmax ----
        float mx[4], rs[4];
        #pragma unroll
        for (int i = 0; i < 4; i++) {
            float m2 = fmaxf(fmaxf(s[i][0], s[i][1]), fmaxf(s[i][2], s[i][3]));
            #pragma unroll
            for (int o = 1; o < 16; o <<= 1)
                m2 = fmaxf(m2, __shfl_xor_sync(0xffffffffu, m2, o));
            mx[i] = m2;
        }
        #pragma unroll
        for (int i = 0; i < 4; i++) {
            float mn = fmaxf(mr[i], mx[i]);
            float al = __expf(mr[i] - mn);
            mr[i] = mn;
            float r = 0.f;
            #pragma unroll
            for (int j = 0; j < 4; j++) {
                float p = __expf(s[i][j] - mn);
                s[i][j] = p; r += p;
            }
            #pragma unroll
            for (int o = 1; o < 16; o <<= 1)
                r += __shfl_xor_sync(0xffffffffu, r, o);
            rs[i] = r;
            lr[i] = lr[i]*al + r;
            #pragma unroll
            for (int j = 0; j < 8; j++) O[i][j] *= al;
        }
        // ---- write P ----
        #pragma unroll
        for (int i = 0; i < 4; i++)
            #pragma unroll
            for (int j = 0; j < 4; j++)
                Ps[(ty*4 + i)*65 + tx*4 + j] = s[i][j];
        __syncthreads();   // P visible; K reads done
        // ---- load V tile into same buffer (stride 128) ----
        const float* Vg = g_V + (long)(b*cT + kt*64)*cE;
        #pragma unroll
        for (int i = 0; i < 8; i++) {
            int idx = tid + i*256;
            int r = idx >> 5, e4 = (idx & 31) << 2;
            *(float4*)(KVs + r*128 + e4) = *(const float4*)(Vg + r*cE + e4);
        }
        __syncthreads();
        // ---- O += P V ----
        #pragma unroll 2
        for (int kk = 0; kk < 64; kk++) {
            float4 v0 = *(float4*)(KVs + kk*128 + tx*4);
            float4 v1 = *(float4*)(KVs + kk*128 + 64 + tx*4);
            #pragma unroll
            for (int i = 0; i < 4; i++) {
                float p = Ps[(ty*4 + i)*65 + kk];
                O[i][0] += p*v0.x; O[i][1] += p*v0.y;
                O[i][2] += p*v0.z; O[i][3] += p*v0.w;
                O[i][4] += p*v1.x; O[i][5] += p*v1.y;
                O[i][6] += p*v1.z; O[i][7] += p*v1.w;
            }
        }
        __syncthreads();   // before next K overwrites buffer
    }
    // ---- normalize, store AH ----
    float* AHg = g_AH + (long)(b*cT + q0)*cE;
    #pragma unroll
    for (int i = 0; i < 4; i++) {
        float inv = 1.f / lr[i];
        float4 o0 = make_float4(O[i][0]*inv, O[i][1]*inv, O[i][2]*inv, O[i][3]*inv);
        float4 o1 = make_float4(O[i][4]*inv, O[i][5]*inv, O[i][6]*inv, O[i][7]*inv);
        float* op = AHg + (long)(ty*4 + i)*cE;
        *(float4*)(op + tx*4)      = o0;
        *(float4*)(op + 64 + tx*4) = o1;
    }
}

// ---------------- fold Wo @ om_W1[0:128,:] ----------------
__global__ void wow1_kernel(const float* __restrict__ Wo, const float* __restrict__ W1) {
    int i = blockIdx.x, j = threadIdx.x;
    float s = 0.f;
    for (int e = 0; e < cE; e++) s += Wo[i*cE + e] * W1[e*cHID + j];
    g_WoW1[i*cHID + j] = s;
}

__global__ void db_kernel(const int* __restrict__ dest, const float* __restrict__ emb,
                          const float* __restrict__ W1) {
    int b = blockIdx.x, j = threadIdx.x;
    int d = dest[b];
    float s = 0.f;
    for (int e = 0; e < cE; e++) s += emb[(long)d*cE + e] * W1[(228+e)*cHID + j];
    g_Db[b*cHID + j] = s;
}

__global__ void consts_kernel(const float* __restrict__ distW, const float* __restrict__ distb,
                              const float* __restrict__ dirW,  const float* __restrict__ dirb,
                              const float* __restrict__ ttW,   const float* __restrict__ ttb,
                              const float* __restrict__ obW1,  const float* __restrict__ omb1,
                              const float* __restrict__ W1) {
    int j = threadIdx.x;
    if (j < cHID) {
        float ad = 0, ax = 0, ay = 0, cv = omb1[j];
        for (int f = 0; f < 50; f++) {
            float wd = W1[(128+f)*cHID + j];
            float wr = W1[(178+f)*cHID + j];
            ad += distW[f]*wd;  cv += distb[f]*wd;
            ax += dirW[f]*wr;   ay += dirW[50+f]*wr;  cv += dirb[f]*wr;
        }
        g_Ad[j] = ad; g_Ax[j] = ax; g_Ay[j] = ay; g_Cv[j] = cv;
    }
    if (j < 25) {
        float u = 0, w = 0;
        for (int f = 0; f < 50; f++) {
            u += ttW[f]*obW1[f*25 + j];
            w += ttb[f]*obW1[f*25 + j];
        }
        g_u1[j] = u; g_w1b[j] = w;
    }
}

// ---------------- masked travel-time statistics ----------------
__global__ void stats_kernel(const int* __restrict__ xs, const int* __restrict__ lengths,
                             const int* __restrict__ adj, const int* __restrict__ seg,
                             const float* __restrict__ TD, const int* __restrict__ stp) {
    int b = blockIdx.x, tid = threadIdx.x;
    int len = lengths[b], st = stp[0];
    float s = 0.f, ss = 0.f, c = 0.f;
    for (int i = tid; i < cTM1*cDEG; i += 256) {
        int t = i >> 3;
        if (t >= len - 1) continue;
        int d = i & 7;
        int x = xs[b*cT + t];
        int a = adj[x*cDEG + d];
        if (a != 0) {
            float tt = TD[(long)seg[x*cDEG + d]*cNBUCKET + st];
            s += tt; ss += tt*tt; c += 1.f;
        }
    }
    __shared__ float r0[256], r1[256], r2[256];
    r0[tid] = s; r1[tid] = ss; r2[tid] = c;
    __syncthreads();
    for (int o = 128; o > 0; o >>= 1) {
        if (tid < o) { r0[tid] += r0[tid+o]; r1[tid] += r1[tid+o]; r2[tid] += r2[tid+o]; }
        __syncthreads();
    }
    if (tid == 0) {
        atomicAdd(&g_stats[0], r0[0]);
        atomicAdd(&g_stats[1], r1[0]);
        atomicAdd(&g_stats[2], r2[0]);
    }
}

__global__ void fin_stats_kernel() {
    float s = g_stats[0], ss = g_stats[1], c = g_stats[2];
    float mean = s / c;
    float var = (ss - c*mean*mean) / (c - 1.f);
    g_white[0] = mean;
    g_white[1] = 1.f / (sqrtf(var) + 1e-6f);
}

// ---------------- batched MLP + NLL: block = (t-chunk, b) ----------------
__global__ __launch_bounds__(256)
void mlp_kernel(const int* __restrict__ xs, const int* __restrict__ lengths,
                const int* __restrict__ acts, const int* __restrict__ dest,
                const int* __restrict__ adj, const int* __restrict__ seg,
                const int* __restrict__ stp, const float* __restrict__ loc,
                const float* __restrict__ TD,
                const float* __restrict__ W2, const float* __restrict__ b2,
                const float* __restrict__ W3, const float* __restrict__ b3,
                const float* __restrict__ obb1, const float* __restrict__ obW2,
                const float* __restrict__ obb2) {
    int b = blockIdx.y;
    int len = lengths[b];
    int t0 = blockIdx.x * 64;
    int tmax = min(t0 + 64, len - 1);
    if (t0 >= tmax) return;

    __shared__ float sW2[cHID*50];
    __shared__ float sh1[cDEG][cHID];
    __shared__ float sDbC[cHID], sAd[cHID], sAx[cHID], sAy[cHID];
    __shared__ float sW3[50], sb2[50];
    __shared__ float su1[25], sw1b[25], sobW2[25], sobb1[25];
    __shared__ float slog[cDEG];

    int tid = threadIdx.x;
    for (int i = tid; i < cHID*50; i += 256) sW2[i] = W2[i];
    if (tid < cHID) {
        sDbC[tid] = g_Db[b*cHID + tid] + g_Cv[tid];
        sAd[tid] = g_Ad[tid]; sAx[tid] = g_Ax[tid]; sAy[tid] = g_Ay[tid];
    }
    if (tid < 50) { sW3[tid] = W3[tid]; sb2[tid] = b2[tid]; }
    if (tid < 25) { su1[tid] = g_u1[tid]; sw1b[tid] = g_w1b[tid];
                    sobW2[tid] = obW2[tid]; sobb1[tid] = obb1[tid]; }
    __syncthreads();

    int d = tid >> 5, lane = tid & 31;
    int db_ = dest[b];
    float dx = loc[db_*2], dy = loc[db_*2 + 1];
    float wm = g_white[0], wi = g_white[1];
    int st = stp[0];
    float lb = b3[0] + obb2[0];
    float bsum = 0.f;

    for (int t = t0; t < tmax; t++) {
        int x = xs[b*cT + t];
        int nb = adj[x*cDEG + d];
        float nx = loc[nb*2], ny = loc[nb*2 + 1];
        float cx = loc[x*2],  cy = loc[x*2 + 1];
        float dist = (fabsf(nx - dx) + fabsf(ny - dy)) * 100.f;
        float vx = nx - cx, vy = ny - cy;
        float inv = 1.f / (sqrtf(vx*vx + vy*vy) + 1e-8f);
        float ux = vx*inv, uy = vy*inv;

        const float* Hrow = g_Hc + (long)(b*cT + t)*cHID;
        for (int j = lane; j < cHID; j += 32) {
            float h = Hrow[j] + sDbC[j] + dist*sAd[j] + ux*sAx[j] + uy*sAy[j];
            sh1[d][j] = fmaxf(h, 0.f);
        }
        __syncwarp();

        float part = 0.f;
        for (int i = lane; i < 50; i += 32) {
            float acc = sb2[i];
            #pragma unroll 4
            for (int j = 0; j < cHID; j++) acc += sh1[d][j] * sW2[j*50 + i];
            part += fmaxf(acc, 0.f) * sW3[i];
        }
        float mf = (nb != 0) ? 1.f : 0.f;
        float tt = TD[(long)seg[x*cDEG + d]*cNBUCKET + st];
        float ttw = (tt - wm) * wi;
        for (int i = lane; i < 25; i += 32) {
            float z = mf*(ttw*su1[i] + sw1b[i]) + sobb1[i];
            part += fmaxf(z, 0.f) * sobW2[i];
        }
        for (int o = 16; o > 0; o >>= 1) part += __shfl_xor_sync(0xffffffffu, part, o);
        if (lane == 0) slog[d] = part + lb;
        __syncthreads();

        if (tid == 0) {
            float m = slog[0];
            #pragma unroll
            for (int i = 1; i < cDEG; i++) m = fmaxf(m, slog[i]);
            float s = 0.f;
            #pragma unroll
            for (int i = 0; i < cDEG; i++) s += __expf(slog[i] - m);
            int a = acts[b*cTM1 + t];
            bsum += (m + __logf(s)) - slog[a];
        }
        __syncthreads();
    }
    if (tid == 0) atomicAdd(&g_per[b], bsum);
}

// ---------------- final reduce ----------------
__global__ void final_kernel(const int* __restrict__ lengths, float* __restrict__ out) {
    __shared__ float r[64];
    int t = threadIdx.x;
    r[t] = g_per[t] / (float)(lengths[t] - 1);
    __syncthreads();
    for (int o = 32; o > 0; o >>= 1) {
        if (t < o) r[t] += r[t + o];
        __syncthreads();
    }
    if (t == 0) out[0] = r[0];
}

// ---------------- launch ----------------
extern "C" void kernel_launch(void* const* d_in, const int* in_sizes, int n_in,
                              void* d_out, int out_size) {
    const int*   xs      = (const int*)  d_in[0];
    const int*   lengths = (const int*)  d_in[1];
    const int*   acts    = (const int*)  d_in[2];
    const int*   dest    = (const int*)  d_in[3];
    const int*   adj     = (const int*)  d_in[4];
    const int*   seg     = (const int*)  d_in[5];
    const int*   stp     = (const int*)  d_in[6];
    const float* loc     = (const float*)d_in[7];
    const float* TD      = (const float*)d_in[8];
    const float* emb     = (const float*)d_in[9];
    const float* Wq      = (const float*)d_in[10];
    const float* Wk      = (const float*)d_in[11];
    const float* Wv      = (const float*)d_in[12];
    const float* Wo      = (const float*)d_in[13];
    const float* distW   = (const float*)d_in[14];
    const float* distb   = (const float*)d_in[15];
    const float* dirW    = (const float*)d_in[16];
    const float* dirb    = (const float*)d_in[17];
    const float* ttW     = (const float*)d_in[18];
    const float* ttb     = (const float*)d_in[19];
    const float* obW1    = (const float*)d_in[20];
    const float* obb1    = (const float*)d_in[21];
    const float* obW2    = (const float*)d_in[22];
    const float* obb2    = (const float*)d_in[23];
    const float* W1      = (const float*)d_in[24];
    const float* omb1    = (const float*)d_in[25];
    const float* W2      = (const float*)d_in[26];
    const float* b2      = (const float*)d_in[27];
    const float* W3      = (const float*)d_in[28];
    const float* b3      = (const float*)d_in[29];

    float *pX, *pQ, *pK, *pV, *pAH, *pHc, *pWoW1;
    cudaGetSymbolAddress((void**)&pX,  g_X);
    cudaGetSymbolAddress((void**)&pQ,  g_Q);
    cudaGetSymbolAddress((void**)&pK,  g_K);
    cudaGetSymbolAddress((void**)&pV,  g_V);
    cudaGetSymbolAddress((void**)&pAH, g_AH);
    cudaGetSymbolAddress((void**)&pHc, g_Hc);
    cudaGetSymbolAddress((void**)&pWoW1, g_WoW1);

    const int ASMEM = (2*64*129 + 64*65) * 4;   // 82688 B
    cudaFuncSetAttribute(attn_kernel, cudaFuncAttributeMaxDynamicSharedMemorySize, ASMEM);

    init_kernel<<<1, 64>>>();
    gather_kernel<<<cB*cT/8, 256>>>(xs, emb);

    // fused QKV
    gemm128<<<dim3(3, 128), 256>>>(pX, Wq, Wk, Wv, pQ, pK, pV, lengths, cE, 1);

    // fused flash attention (length-aware)
    attn_kernel<<<dim3(4, cB), 256, ASMEM>>>(lengths);

    wow1_kernel<<<cE, cHID>>>(Wo, W1);
    db_kernel<<<cB, cHID>>>(dest, emb, W1);
    consts_kernel<<<1, 128>>>(distW, distb, dirW, dirb, ttW, ttb, obW1, omb1, W1);

    // Hc = AH @ (Wo @ W1[:128])
    gemm128<<<dim3(1, 128), 256>>>(pAH, pWoW1, nullptr, nullptr,
                                   pHc, nullptr, nullptr, lengths, cHID, 2);

    stats_kernel<<<cB, 256>>>(xs, lengths, adj, seg, TD, stp);
    fin_stats_kernel<<<1, 1>>>();

    mlp_kernel<<<dim3(4, cB), 256>>>(xs, lengths, acts, dest, adj, seg, stp, loc, TD,
                                     W2, b2, W3, b3, obb1, obW2, obb2);
    final_kernel<<<1, 64>>>(lengths, (float*)d_out);
}

// round 7
// speedup vs baseline: 1.0782x; 1.0782x over previous
#include <cuda_runtime.h>
#include <math.h>

constexpr int cB = 64, cT = 256, cE = 128, cDEG = 8, cHID = 100;
constexpr int cTM1 = 255, cNBUCKET = 288;

// ---------------- device scratch ----------------
__device__ float g_Q [cB*cT*cE];
__device__ float g_K [cB*cT*cE];
__device__ float g_V [cB*cT*cE];
__device__ float g_AH[cB*cT*cE];
__device__ float g_Hc[cB*cT*cHID];
__device__ float g_WoW1[cE*cHID];
__device__ float g_Db[cB*cHID];
__device__ float g_Ad[cHID], g_Ax[cHID], g_Ay[cHID], g_Cv[cHID];
__device__ float g_u1[25], g_w1b[25];
__device__ float g_sparts[cB*3];     // per-batch stats partials
__device__ float g_pparts[4*cB];     // per (chunk,b) NLL partials
__device__ float g_per[cB];          // unused placeholder (kept for layout stability)

// ================= setup: wow1 | db | consts | stats, one kernel =================
__global__ void setup_kernel(const float* __restrict__ Wo, const float* __restrict__ W1,
                             const int* __restrict__ dest, const float* __restrict__ emb,
                             const float* __restrict__ distW, const float* __restrict__ distb,
                             const float* __restrict__ dirW,  const float* __restrict__ dirb,
                             const float* __restrict__ ttW,   const float* __restrict__ ttb,
                             const float* __restrict__ obW1,  const float* __restrict__ omb1,
                             const int* __restrict__ xs, const int* __restrict__ lengths,
                             const int* __restrict__ adj, const int* __restrict__ seg,
                             const float* __restrict__ TD, const int* __restrict__ stp) {
    __shared__ float r0[128], r1[128], r2[128];
    int blk = blockIdx.x, tid = threadIdx.x;
    if (blk < 128) {                       // WoW1 row = blk
        if (tid < cHID) {
            float s = 0.f;
            for (int e = 0; e < cE; e++) s += Wo[blk*cE + e] * W1[e*cHID + tid];
            g_WoW1[blk*cHID + tid] = s;
        }
    } else if (blk < 192) {                // Db for b = blk-128
        if (tid < cHID) {
            int b = blk - 128, d = dest[b];
            float s = 0.f;
            for (int e = 0; e < cE; e++) s += emb[(long)d*cE + e] * W1[(228+e)*cHID + tid];
            g_Db[b*cHID + tid] = s;
        }
    } else if (blk == 192) {               // small constant vectors
        int j = tid;
        if (j < cHID) {
            float ad = 0, ax = 0, ay = 0, cv = omb1[j];
            for (int f = 0; f < 50; f++) {
                float wd = W1[(128+f)*cHID + j];
                float wr = W1[(178+f)*cHID + j];
                ad += distW[f]*wd;  cv += distb[f]*wd;
                ax += dirW[f]*wr;   ay += dirW[50+f]*wr;  cv += dirb[f]*wr;
            }
            g_Ad[j] = ad; g_Ax[j] = ax; g_Ay[j] = ay; g_Cv[j] = cv;
        }
        if (j < 25) {
            float u = 0, w = 0;
            for (int f = 0; f < 50; f++) {
                u += ttW[f]*obW1[f*25 + j];
                w += ttb[f]*obW1[f*25 + j];
            }
            g_u1[j] = u; g_w1b[j] = w;
        }
    } else {                               // stats partial for b = blk-193
        int b = blk - 193;
        int len = lengths[b], st = stp[0];
        float s = 0.f, ss = 0.f, c = 0.f;
        for (int i = tid; i < cTM1*cDEG; i += 128) {
            int t = i >> 3;
            if (t >= len - 1) continue;
            int d = i & 7;
            int x = xs[b*cT + t];
            int a = adj[x*cDEG + d];
            if (a != 0) {
                float tt = TD[(long)seg[x*cDEG + d]*cNBUCKET + st];
                s += tt; ss += tt*tt; c += 1.f;
            }
        }
        r0[tid] = s; r1[tid] = ss; r2[tid] = c;
        __syncthreads();
        for (int o = 64; o > 0; o >>= 1) {
            if (tid < o) { r0[tid] += r0[tid+o]; r1[tid] += r1[tid+o]; r2[tid] += r2[tid+o]; }
            __syncthreads();
        }
        if (tid == 0) {
            g_sparts[b*3]   = r0[0];
            g_sparts[b*3+1] = r1[0];
            g_sparts[b*3+2] = r2[0];
        }
    }
}

// ================= 128-row-tile GEMM, 8x8 register tiles, pipelined =================
// If xsg != null: A rows are gathered from emb[xsg[row]] (QKV path, N=128, 3 outputs).
// Else plain A (Hc path, N<=128). skipmode 1: skip if t0>=ceil64(len); 2: t0>=len-1.
__global__ __launch_bounds__(256)
void gemm128(const float* __restrict__ A, const int* __restrict__ xsg,
             const float* __restrict__ emb,
             const float* __restrict__ B0, const float* __restrict__ B1,
             const float* __restrict__ B2,
             float* __restrict__ C0, float* __restrict__ C1, float* __restrict__ C2,
             const int* __restrict__ lengths, int N, int skipmode) {
    int m0 = blockIdx.y * 128;
    int b  = m0 >> 8, t0 = m0 & 255;
    int len = lengths[b];
    if (skipmode == 1 && t0 >= ((len + 63) & ~63)) return;
    if (skipmode == 2 && t0 >= len - 1) return;
    const float* Bm = (blockIdx.x == 0) ? B0 : (blockIdx.x == 1 ? B1 : B2);
    float*       C  = (blockIdx.x == 0) ? C0 : (blockIdx.x == 1 ? C1 : C2);

    __shared__ float As[128*17];
    __shared__ float Bs[17*128];           // 1 pad row for prefetch overrun
    __shared__ int   sXs[128];
    int tid = threadIdx.x;
    int tx = tid & 15, ty = tid >> 4;

    if (xsg && tid < 128) sXs[tid] = xsg[m0 + tid];
    __syncthreads();

    int rA = tid >> 1, cA = (tid & 1) * 8;
    const float* arow = xsg ? emb + (long)sXs[rA]*cE
                            : A + (long)(m0 + rA)*cE;

    float acc[8][8] = {};
    for (int k0 = 0; k0 < 128; k0 += 16) {
        {   // A tile [128][16] -> As (pad 17)
            const float* ap = arow + k0 + cA;
            float4 v0 = *(const float4*)ap;
            float4 v1 = *(const float4*)(ap + 4);
            float* as = As + rA*17 + cA;
            as[0]=v0.x; as[1]=v0.y; as[2]=v0.z; as[3]=v0.w;
            as[4]=v1.x; as[5]=v1.y; as[6]=v1.z; as[7]=v1.w;
        }
        {   // B tile [16][N<=128] -> Bs
            int r = tid >> 4, c = (tid & 15) * 8;
            float4 z = make_float4(0.f,0.f,0.f,0.f);
            const float* bp = Bm + (long)(k0 + r)*N + c;
            float4 v0 = (c     < N) ? *(const float4*)bp       : z;
            float4 v1 = (c + 4 < N) ? *(const float4*)(bp + 4) : z;
            *(float4*)(Bs + r*128 + c)     = v0;
            *(float4*)(Bs + r*128 + c + 4) = v1;
        }
        __syncthreads();
        // pipelined 8x8 MACs over 16 kk
        float ac[8], bc[8];
        #pragma unroll
        for (int i = 0; i < 4; i++) {
            ac[i]   = As[(ty*4 + i)*17];
            ac[4+i] = As[(64 + ty*4 + i)*17];
        }
        {
            float4 u0 = *(float4*)(Bs + tx*4), u1 = *(float4*)(Bs + 64 + tx*4);
            bc[0]=u0.x; bc[1]=u0.y; bc[2]=u0.z; bc[3]=u0.w;
            bc[4]=u1.x; bc[5]=u1.y; bc[6]=u1.z; bc[7]=u1.w;
        }
        #pragma unroll
        for (int kk = 0; kk < 16; kk += 2) {
            float an[8], bn[8];
            #pragma unroll
            for (int i = 0; i < 4; i++) {
                an[i]   = As[(ty*4 + i)*17 + kk + 1];
                an[4+i] = As[(64 + ty*4 + i)*17 + kk + 1];
            }
            {
                float4 u0 = *(float4*)(Bs + (kk+1)*128 + tx*4);
                float4 u1 = *(float4*)(Bs + (kk+1)*128 + 64 + tx*4);
                bn[0]=u0.x; bn[1]=u0.y; bn[2]=u0.z; bn[3]=u0.w;
                bn[4]=u1.x; bn[5]=u1.y; bn[6]=u1.z; bn[7]=u1.w;
            }
            #pragma unroll
            for (int i = 0; i < 8; i++)
                #pragma unroll
                for (int j = 0; j < 8; j++)
                    acc[i][j] += ac[i]*bc[j];
            #pragma unroll
            for (int i = 0; i < 4; i++) {              // kk+2 (pad col at 16 is safe)
                ac[i]   = As[(ty*4 + i)*17 + kk + 2];
                ac[4+i] = As[(64 + ty*4 + i)*17 + kk + 2];
            }
            {
                float4 u0 = *(float4*)(Bs + (kk+2)*128 + tx*4);   // pad row 16 safe
                float4 u1 = *(float4*)(Bs + (kk+2)*128 + 64 + tx*4);
                bc[0]=u0.x; bc[1]=u0.y; bc[2]=u0.z; bc[3]=u0.w;
                bc[4]=u1.x; bc[5]=u1.y; bc[6]=u1.z; bc[7]=u1.w;
            }
            #pragma unroll
            for (int i = 0; i < 8; i++)
                #pragma unroll
                for (int j = 0; j < 8; j++)
                    acc[i][j] += an[i]*bn[j];
        }
        __syncthreads();
    }
    #pragma unroll
    for (int i = 0; i < 8; i++) {
        int row = m0 + ((i < 4) ? (ty*4 + i) : (64 + ty*4 + i - 4));
        float* cp = C + (long)row*N;
        int c0 = tx*4, c1 = 64 + tx*4;
        float4 o0 = make_float4(acc[i][0],acc[i][1],acc[i][2],acc[i][3]);
        float4 o1 = make_float4(acc[i][4],acc[i][5],acc[i][6],acc[i][7]);
        if (c0 < N) *(float4*)(cp + c0) = o0;
        if (c1 < N) *(float4*)(cp + c1) = o1;
    }
}

// ================= fused flash attention (pipelined) =================
__global__ __launch_bounds__(256)
void attn_kernel(const int* __restrict__ lengths) {
    extern __shared__ float sm[];
    float* Qs = sm;               // [64][129]
    float* KVs = sm + 64*129;     // K stride 129 / V stride 128
    float* Ps = sm + 2*64*129;    // [64][65]

    int b  = blockIdx.y;
    int qt = 3 - blockIdx.x;
    int q0 = qt * 64;
    int len = lengths[b];
    if (q0 >= len) return;

    int tid = threadIdx.x;
    int tx = tid & 15, ty = tid >> 4;
    const float scale = 0.08838834764831845f;

    const float* Qg = g_Q + (long)(b*cT + q0)*cE;
    #pragma unroll
    for (int i = 0; i < 8; i++) {
        int idx = tid + i*256;
        int r = idx >> 5, e4 = (idx & 31) << 2;
        float4 v = *(const float4*)(Qg + r*cE + e4);
        float* qs = Qs + r*129 + e4;
        qs[0]=v.x*scale; qs[1]=v.y*scale; qs[2]=v.z*scale; qs[3]=v.w*scale;
    }
    float O[4][8] = {};
    float mr[4], lr[4];
    #pragma unroll
    for (int i = 0; i < 4; i++) { mr[i] = -1e30f; lr[i] = 0.f; }
    __syncthreads();

    int ktmax = min(qt, ((len + 63) >> 6) - 1);
    for (int kt = 0; kt <= ktmax; kt++) {
        const float* Kg = g_K + (long)(b*cT + kt*64)*cE;
        #pragma unroll
        for (int i = 0; i < 8; i++) {
            int idx = tid + i*256;
            int r = idx >> 5, e4 = (idx & 31) << 2;
            float4 v = *(const float4*)(Kg + r*cE + e4);
            float* ks = KVs + r*129 + e4;
            ks[0]=v.x; ks[1]=v.y; ks[2]=v.z; ks[3]=v.w;
        }
        __syncthreads();
        // ---- S = Q K^T, double-buffered ----
        float s[4][4] = {};
        float a0[4], b0[4];
        #pragma unroll
        for (int i = 0; i < 4; i++) {
            a0[i] = Qs[(ty*4 + i)*129];
            b0[i] = KVs[(tx*4 + i)*129];
        }
        #pragma unroll 4
        for (int kk = 0; kk < 128; kk += 2) {
            float a1[4], b1[4];
            #pragma unroll
            for (int i = 0; i < 4; i++) {
                a1[i] = Qs[(ty*4 + i)*129 + kk + 1];
                b1[i] = KVs[(tx*4 + i)*129 + kk + 1];
            }
            #pragma unroll
            for (int i = 0; i < 4; i++)
                #pragma unroll
                for (int j = 0; j < 4; j++)
                    s[i][j] += a0[i]*b0[j];
            #pragma unroll
            for (int i = 0; i < 4; i++) {          // kk+2 == 128 hits pad col, safe
                a0[i] = Qs[(ty*4 + i)*129 + kk + 2];
                b0[i] = KVs[(tx*4 + i)*129 + kk + 2];
            }
            #pragma unroll
            for (int i = 0; i < 4; i++)
                #pragma unroll
                for (int j = 0; j < 4; j++)
                    s[i][j] += a1[i]*b1[j];
        }
        // ---- mask ----
        int kbase = kt*64;
        bool diag = (kt == qt);
        #pragma unroll
        for (int i = 0; i < 4; i++) {
            int q = q0 + ty*4 + i;
            #pragma unroll
            for (int j = 0; j < 4; j++) {
                int k = kbase + tx*4 + j;
                if ((diag && k > q) || k >= len) s[i][j] = -1e30f;
            }
        }
        // ---- online softmax ----
        #pragma unroll
        for (int i = 0; i < 4; i++) {
            float m2 = fmaxf(fmaxf(s[i][0], s[i][1]), fmaxf(s[i][2], s[i][3]));
            #pragma unroll
            for (int o = 1; o < 16; o <<= 1)
                m2 = fmaxf(m2, __shfl_xor_sync(0xffffffffu, m2, o));
            float mn = fmaxf(mr[i], m2);
            float al = __expf(mr[i] - mn);
            mr[i] = mn;
            float r = 0.f;
            #pragma unroll
            for (int j = 0; j < 4; j++) {
                float p = __expf(s[i][j] - mn);
                s[i][j] = p; r += p;
            }
            #pragma unroll
            for (int o = 1; o < 16; o <<= 1)
                r += __shfl_xor_sync(0xffffffffu, r, o);
            lr[i] = lr[i]*al + r;
            #pragma unroll
            for (int j = 0; j < 8; j++) O[i][j] *= al;
        }
        #pragma unroll
        for (int i = 0; i < 4; i++)
            #pragma unroll
            for (int j = 0; j < 4; j++)
                Ps[(ty*4 + i)*65 + tx*4 + j] = s[i][j];
        __syncthreads();
        // ---- V tile (stride 128, reuse KVs) ----
        const float* Vg = g_V + (long)(b*cT + kt*64)*cE;
        #pragma unroll
        for (int i = 0; i < 8; i++) {
            int idx = tid + i*256;
            int r = idx >> 5, e4 = (idx & 31) << 2;
            *(float4*)(KVs + r*128 + e4) = *(const float4*)(Vg + r*cE + e4);
        }
        __syncthreads();
        // ---- O += P V, double-buffered ----
        float p0[4];
        float4 u0, u1;
        #pragma unroll
        for (int i = 0; i < 4; i++) p0[i] = Ps[(ty*4 + i)*65];
        u0 = *(float4*)(KVs + tx*4);
        u1 = *(float4*)(KVs + 64 + tx*4);
        #pragma unroll 4
        for (int kk = 0; kk < 64; kk += 2) {
            float p1[4]; float4 w0, w1;
            #pragma unroll
            for (int i = 0; i < 4; i++) p1[i] = Ps[(ty*4 + i)*65 + kk + 1];
            w0 = *(float4*)(KVs + (kk+1)*128 + tx*4);
            w1 = *(float4*)(KVs + (kk+1)*128 + 64 + tx*4);
            #pragma unroll
            for (int i = 0; i < 4; i++) {
                O[i][0] += p0[i]*u0.x; O[i][1] += p0[i]*u0.y;
                O[i][2] += p0[i]*u0.z; O[i][3] += p0[i]*u0.w;
                O[i][4] += p0[i]*u1.x; O[i][5] += p0[i]*u1.y;
                O[i][6] += p0[i]*u1.z; O[i][7] += p0[i]*u1.w;
            }
            #pragma unroll
            for (int i = 0; i < 4; i++) p0[i] = Ps[(ty*4 + i)*65 + kk + 2]; // pad safe
            u0 = *(float4*)(KVs + (kk+2)*128 + tx*4);      // overruns into Ps, unused
            u1 = *(float4*)(KVs + (kk+2)*128 + 64 + tx*4);
            #pragma unroll
            for (int i = 0; i < 4; i++) {
                O[i][0] += p1[i]*w0.x; O[i][1] += p1[i]*w0.y;
                O[i][2] += p1[i]*w0.z; O[i][3] += p1[i]*w0.w;
                O[i][4] += p1[i]*w1.x; O[i][5] += p1[i]*w1.y;
                O[i][6] += p1[i]*w1.z; O[i][7] += p1[i]*w1.w;
            }
        }
        __syncthreads();
    }
    float* AHg = g_AH + (long)(b*cT + q0)*cE;
    #pragma unroll
    for (int i = 0; i < 4; i++) {
        float inv = 1.f / lr[i];
        float4 o0 = make_float4(O[i][0]*inv, O[i][1]*inv, O[i][2]*inv, O[i][3]*inv);
        float4 o1 = make_float4(O[i][4]*inv, O[i][5]*inv, O[i][6]*inv, O[i][7]*inv);
        float* op = AHg + (long)(ty*4 + i)*cE;
        *(float4*)(op + tx*4)      = o0;
        *(float4*)(op + 64 + tx*4) = o1;
    }
}

// ================= batched MLP + NLL, deterministic partials =================
__global__ __launch_bounds__(256)
void mlp_kernel(const int* __restrict__ xs, const int* __restrict__ lengths,
                const int* __restrict__ acts, const int* __restrict__ dest,
                const int* __restrict__ adj, const int* __restrict__ seg,
                const int* __restrict__ stp, const float* __restrict__ loc,
                const float* __restrict__ TD,
                const float* __restrict__ W2, const float* __restrict__ b2,
                const float* __restrict__ W3, const float* __restrict__ b3,
                const float* __restrict__ obb1, const float* __restrict__ obW2,
                const float* __restrict__ obb2) {
    int b = blockIdx.y;
    int len = lengths[b];
    int t0 = blockIdx.x * 64;
    int tmax = min(t0 + 64, len - 1);
    int tid = threadIdx.x;
    if (t0 >= tmax) {
        if (tid == 0) g_pparts[blockIdx.x*cB + b] = 0.f;
        return;
    }

    __shared__ float sW2[cHID*50];
    __shared__ float sh1[cDEG][cHID];
    __shared__ float sDbC[cHID], sAd[cHID], sAx[cHID], sAy[cHID];
    __shared__ float sW3[50], sb2[50];
    __shared__ float su1[25], sw1b[25], sobW2[25], sobb1[25];
    __shared__ float slog[cDEG];
    __shared__ float sst[192];
    __shared__ float swhite[2];

    for (int i = tid; i < cHID*50; i += 256) sW2[i] = W2[i];
    if (tid < 64) {
        sst[tid]      = g_sparts[tid*3];
        sst[64+tid]   = g_sparts[tid*3+1];
        sst[128+tid]  = g_sparts[tid*3+2];
    }
    if (tid < cHID) {
        sDbC[tid] = g_Db[b*cHID + tid] + g_Cv[tid];
        sAd[tid] = g_Ad[tid]; sAx[tid] = g_Ax[tid]; sAy[tid] = g_Ay[tid];
    }
    if (tid < 50) { sW3[tid] = W3[tid]; sb2[tid] = b2[tid]; }
    if (tid < 25) { su1[tid] = g_u1[tid]; sw1b[tid] = g_w1b[tid];
                    sobW2[tid] = obW2[tid]; sobb1[tid] = obb1[tid]; }
    __syncthreads();
    if (tid == 0) {
        float s = 0.f, ss = 0.f, c = 0.f;
        for (int i = 0; i < 64; i++) { s += sst[i]; ss += sst[64+i]; c += sst[128+i]; }
        float mean = s / c;
        float var = (ss - c*mean*mean) / (c - 1.f);
        swhite[0] = mean;
        swhite[1] = 1.f / (sqrtf(var) + 1e-6f);
    }
    __syncthreads();

    int d = tid >> 5, lane = tid & 31;
    int db_ = dest[b];
    float dx = loc[db_*2], dy = loc[db_*2 + 1];
    float wm = swhite[0], wi = swhite[1];
    int st = stp[0];
    float lb = b3[0] + obb2[0];
    float bsum = 0.f;

    for (int t = t0; t < tmax; t++) {
        int x = xs[b*cT + t];
        int nb = adj[x*cDEG + d];
        float nx = loc[nb*2], ny = loc[nb*2 + 1];
        float cx = loc[x*2],  cy = loc[x*2 + 1];
        float dist = (fabsf(nx - dx) + fabsf(ny - dy)) * 100.f;
        float vx = nx - cx, vy = ny - cy;
        float inv = 1.f / (sqrtf(vx*vx + vy*vy) + 1e-8f);
        float ux = vx*inv, uy = vy*inv;

        const float* Hrow = g_Hc + (long)(b*cT + t)*cHID;
        for (int j = lane; j < cHID; j += 32) {
            float h = Hrow[j] + sDbC[j] + dist*sAd[j] + ux*sAx[j] + uy*sAy[j];
            sh1[d][j] = fmaxf(h, 0.f);
        }
        __syncwarp();

        float part = 0.f;
        for (int i = lane; i < 50; i += 32) {
            float acc = sb2[i];
            #pragma unroll 4
            for (int j = 0; j < cHID; j++) acc += sh1[d][j] * sW2[j*50 + i];
            part += fmaxf(acc, 0.f) * sW3[i];
        }
        float mf = (nb != 0) ? 1.f : 0.f;
        float tt = TD[(long)seg[x*cDEG + d]*cNBUCKET + st];
        float ttw = (tt - wm) * wi;
        for (int i = lane; i < 25; i += 32) {
            float z = mf*(ttw*su1[i] + sw1b[i]) + sobb1[i];
            part += fmaxf(z, 0.f) * sobW2[i];
        }
        for (int o = 16; o > 0; o >>= 1) part += __shfl_xor_sync(0xffffffffu, part, o);
        if (lane == 0) slog[d] = part + lb;
        __syncthreads();

        if (tid == 0) {
            float m = slog[0];
            #pragma unroll
            for (int i = 1; i < cDEG; i++) m = fmaxf(m, slog[i]);
            float s = 0.f;
            #pragma unroll
            for (int i = 0; i < cDEG; i++) s += __expf(slog[i] - m);
            int a = acts[b*cTM1 + t];
            bsum += (m + __logf(s)) - slog[a];
        }
        __syncthreads();
    }
    if (tid == 0) g_pparts[blockIdx.x*cB + b] = bsum;
}

// ---------------- final reduce ----------------
__global__ void final_kernel(const int* __restrict__ lengths, float* __restrict__ out) {
    __shared__ float r[64];
    int t = threadIdx.x;
    float s = g_pparts[t] + g_pparts[cB + t] + g_pparts[2*cB + t] + g_pparts[3*cB + t];
    r[t] = s / (float)(lengths[t] - 1);
    __syncthreads();
    for (int o = 32; o > 0; o >>= 1) {
        if (t < o) r[t] += r[t + o];
        __syncthreads();
    }
    if (t == 0) out[0] = r[0];
}

// ---------------- launch ----------------
extern "C" void kernel_launch(void* const* d_in, const int* in_sizes, int n_in,
                              void* d_out, int out_size) {
    const int*   xs      = (const int*)  d_in[0];
    const int*   lengths = (const int*)  d_in[1];
    const int*   acts    = (const int*)  d_in[2];
    const int*   dest    = (const int*)  d_in[3];
    const int*   adj     = (const int*)  d_in[4];
    const int*   seg     = (const int*)  d_in[5];
    const int*   stp     = (const int*)  d_in[6];
    const float* loc     = (const float*)d_in[7];
    const float* TD      = (const float*)d_in[8];
    const float* emb     = (const float*)d_in[9];
    const float* Wq      = (const float*)d_in[10];
    const float* Wk      = (const float*)d_in[11];
    const float* Wv      = (const float*)d_in[12];
    const float* Wo      = (const float*)d_in[13];
    const float* distW   = (const float*)d_in[14];
    const float* distb   = (const float*)d_in[15];
    const float* dirW    = (const float*)d_in[16];
    const float* dirb    = (const float*)d_in[17];
    const float* ttW     = (const float*)d_in[18];
    const float* ttb     = (const float*)d_in[19];
    const float* obW1    = (const float*)d_in[20];
    const float* obb1    = (const float*)d_in[21];
    const float* obW2    = (const float*)d_in[22];
    const float* obb2    = (const float*)d_in[23];
    const float* W1      = (const float*)d_in[24];
    const float* omb1    = (const float*)d_in[25];
    const float* W2      = (const float*)d_in[26];
    const float* b2      = (const float*)d_in[27];
    const float* W3      = (const float*)d_in[28];
    const float* b3      = (const float*)d_in[29];

    float *pQ, *pK, *pV, *pAH, *pHc, *pWoW1;
    cudaGetSymbolAddress((void**)&pQ,  g_Q);
    cudaGetSymbolAddress((void**)&pK,  g_K);
    cudaGetSymbolAddress((void**)&pV,  g_V);
    cudaGetSymbolAddress((void**)&pAH, g_AH);
    cudaGetSymbolAddress((void**)&pHc, g_Hc);
    cudaGetSymbolAddress((void**)&pWoW1, g_WoW1);

    const int ASMEM = (2*64*129 + 64*65) * 4;   // 82688 B
    cudaFuncSetAttribute(attn_kernel, cudaFuncAttributeMaxDynamicSharedMemorySize, ASMEM);

    // 1) fold-weights + destination features + consts + stats partials
    setup_kernel<<<257, 128>>>(Wo, W1, dest, emb, distW, distb, dirW, dirb,
                               ttW, ttb, obW1, omb1,
                               xs, lengths, adj, seg, TD, stp);

    // 2) fused gather + QKV GEMM
    gemm128<<<dim3(3, 128), 256>>>(nullptr, xs, emb, Wq, Wk, Wv,
                                   pQ, pK, pV, lengths, cE, 1);

    // 3) fused flash attention
    attn_kernel<<<dim3(4, cB), 256, ASMEM>>>(lengths);

    // 4) Hc = AH @ (Wo @ W1[:128])
    gemm128<<<dim3(1, 128), 256>>>(pAH, nullptr, nullptr, pWoW1, nullptr, nullptr,
                                   pHc, nullptr, nullptr, lengths, cHID, 2);

    // 5) fused MLP + neighbor softmax + NLL (deterministic partials)
    mlp_kernel<<<dim3(4, cB), 256>>>(xs, lengths, acts, dest, adj, seg, stp, loc, TD,
                                     W2, b2, W3, b3, obb1, obW2, obb2);

    // 6) final reduction
    final_kernel<<<1, 64>>>(lengths, (float*)d_out);
}

// round 9
// speedup vs baseline: 2.6218x; 2.4315x over previous
#include <cuda_runtime.h>
#include <math.h>

constexpr int cB = 64, cT = 256, cE = 128, cDEG = 8, cHID = 100;
constexpr int cTM1 = 255, cNBUCKET = 288;
constexpr int cCH = 16;               // mlp t-chunks per batch

// ---------------- device scratch ----------------
__device__ float g_Q [cB*cT*cE];
__device__ float g_K [cB*cT*cE];
__device__ float g_V [cB*cT*cE];
__device__ float g_AH[cB*cT*cE];
__device__ float g_Hc[cB*cT*cHID];
__device__ float g_WoW1[cE*cHID];
__device__ float g_Db[cB*cHID];
__device__ float g_Ad[cHID], g_Ax[cHID], g_Ay[cHID], g_Cv[cHID];
__device__ float g_u1[25], g_w1b[25];
__device__ float g_sparts[cB*3];
__device__ float g_pparts[cCH*cB];

// ================= setup: wow1 | db | consts | stats =================
__global__ void setup_kernel(const float* __restrict__ Wo, const float* __restrict__ W1,
                             const int* __restrict__ dest, const float* __restrict__ emb,
                             const float* __restrict__ distW, const float* __restrict__ distb,
                             const float* __restrict__ dirW,  const float* __restrict__ dirb,
                             const float* __restrict__ ttW,   const float* __restrict__ ttb,
                             const float* __restrict__ obW1,  const float* __restrict__ omb1,
                             const int* __restrict__ xs, const int* __restrict__ lengths,
                             const int* __restrict__ adj, const int* __restrict__ seg,
                             const float* __restrict__ TD, const int* __restrict__ stp) {
    __shared__ float r0[128], r1[128], r2[128];
    int blk = blockIdx.x, tid = threadIdx.x;
    if (blk < 128) {
        if (tid < cHID) {
            float s = 0.f;
            for (int e = 0; e < cE; e++) s += Wo[blk*cE + e] * W1[e*cHID + tid];
            g_WoW1[blk*cHID + tid] = s;
        }
    } else if (blk < 192) {
        if (tid < cHID) {
            int b = blk - 128, d = dest[b];
            float s = 0.f;
            for (int e = 0; e < cE; e++) s += emb[(long)d*cE + e] * W1[(228+e)*cHID + tid];
            g_Db[b*cHID + tid] = s;
        }
    } else if (blk == 192) {
        int j = tid;
        if (j < cHID) {
            float ad = 0, ax = 0, ay = 0, cv = omb1[j];
            for (int f = 0; f < 50; f++) {
                float wd = W1[(128+f)*cHID + j];
                float wr = W1[(178+f)*cHID + j];
                ad += distW[f]*wd;  cv += distb[f]*wd;
                ax += dirW[f]*wr;   ay += dirW[50+f]*wr;  cv += dirb[f]*wr;
            }
            g_Ad[j] = ad; g_Ax[j] = ax; g_Ay[j] = ay; g_Cv[j] = cv;
        }
        if (j < 25) {
            float u = 0, w = 0;
            for (int f = 0; f < 50; f++) {
                u += ttW[f]*obW1[f*25 + j];
                w += ttb[f]*obW1[f*25 + j];
            }
            g_u1[j] = u; g_w1b[j] = w;
        }
    } else {
        int b = blk - 193;
        int len = lengths[b], st = stp[0];
        float s = 0.f, ss = 0.f, c = 0.f;
        for (int i = tid; i < cTM1*cDEG; i += 128) {
            int t = i >> 3;
            if (t >= len - 1) continue;
            int d = i & 7;
            int x = xs[b*cT + t];
            int a = adj[x*cDEG + d];
            if (a != 0) {
                float tt = TD[(long)seg[x*cDEG + d]*cNBUCKET + st];
                s += tt; ss += tt*tt; c += 1.f;
            }
        }
        r0[tid] = s; r1[tid] = ss; r2[tid] = c;
        __syncthreads();
        for (int o = 64; o > 0; o >>= 1) {
            if (tid < o) { r0[tid] += r0[tid+o]; r1[tid] += r1[tid+o]; r2[tid] += r2[tid+o]; }
            __syncthreads();
        }
        if (tid == 0) {
            g_sparts[b*3]   = r0[0];
            g_sparts[b*3+1] = r1[0];
            g_sparts[b*3+2] = r2[0];
        }
    }
}

// ================= 128-row-tile GEMM (pipelined 8x8) =================
__global__ __launch_bounds__(256)
void gemm128(const float* __restrict__ A, const int* __restrict__ xsg,
             const float* __restrict__ emb,
             const float* __restrict__ B0, const float* __restrict__ B1,
             const float* __restrict__ B2,
             float* __restrict__ C0, float* __restrict__ C1, float* __restrict__ C2,
             const int* __restrict__ lengths, int N, int skipmode) {
    int m0 = blockIdx.y * 128;
    int b  = m0 >> 8, t0 = m0 & 255;
    int len = lengths[b];
    if (skipmode == 1 && t0 >= ((len + 63) & ~63)) return;
    if (skipmode == 2 && t0 >= len - 1) return;
    const float* Bm = (blockIdx.x == 0) ? B0 : (blockIdx.x == 1 ? B1 : B2);
    float*       C  = (blockIdx.x == 0) ? C0 : (blockIdx.x == 1 ? C1 : C2);

    __shared__ float As[128*17];
    __shared__ float Bs[17*128];
    __shared__ int   sXs[128];
    int tid = threadIdx.x;
    int tx = tid & 15, ty = tid >> 4;

    if (xsg && tid < 128) sXs[tid] = xsg[m0 + tid];
    __syncthreads();

    int rA = tid >> 1, cA = (tid & 1) * 8;
    const float* arow = xsg ? emb + (long)sXs[rA]*cE
                            : A + (long)(m0 + rA)*cE;

    float acc[8][8] = {};
    for (int k0 = 0; k0 < 128; k0 += 16) {
        {
            const float* ap = arow + k0 + cA;
            float4 v0 = *(const float4*)ap;
            float4 v1 = *(const float4*)(ap + 4);
            float* as = As + rA*17 + cA;
            as[0]=v0.x; as[1]=v0.y; as[2]=v0.z; as[3]=v0.w;
            as[4]=v1.x; as[5]=v1.y; as[6]=v1.z; as[7]=v1.w;
        }
        {
            int r = tid >> 4, c = (tid & 15) * 8;
            float4 z = make_float4(0.f,0.f,0.f,0.f);
            const float* bp = Bm + (long)(k0 + r)*N + c;
            float4 v0 = (c     < N) ? *(const float4*)bp       : z;
            float4 v1 = (c + 4 < N) ? *(const float4*)(bp + 4) : z;
            *(float4*)(Bs + r*128 + c)     = v0;
            *(float4*)(Bs + r*128 + c + 4) = v1;
        }
        __syncthreads();
        float ac[8], bc[8];
        #pragma unroll
        for (int i = 0; i < 4; i++) {
            ac[i]   = As[(ty*4 + i)*17];
            ac[4+i] = As[(64 + ty*4 + i)*17];
        }
        {
            float4 u0 = *(float4*)(Bs + tx*4), u1 = *(float4*)(Bs + 64 + tx*4);
            bc[0]=u0.x; bc[1]=u0.y; bc[2]=u0.z; bc[3]=u0.w;
            bc[4]=u1.x; bc[5]=u1.y; bc[6]=u1.z; bc[7]=u1.w;
        }
        #pragma unroll
        for (int kk = 0; kk < 16; kk += 2) {
            float an[8], bn[8];
            #pragma unroll
            for (int i = 0; i < 4; i++) {
                an[i]   = As[(ty*4 + i)*17 + kk + 1];
                an[4+i] = As[(64 + ty*4 + i)*17 + kk + 1];
            }
            {
                float4 u0 = *(float4*)(Bs + (kk+1)*128 + tx*4);
                float4 u1 = *(float4*)(Bs + (kk+1)*128 + 64 + tx*4);
                bn[0]=u0.x; bn[1]=u0.y; bn[2]=u0.z; bn[3]=u0.w;
                bn[4]=u1.x; bn[5]=u1.y; bn[6]=u1.z; bn[7]=u1.w;
            }
            #pragma unroll
            for (int i = 0; i < 8; i++)
                #pragma unroll
                for (int j = 0; j < 8; j++)
                    acc[i][j] += ac[i]*bc[j];
            #pragma unroll
            for (int i = 0; i < 4; i++) {
                ac[i]   = As[(ty*4 + i)*17 + kk + 2];
                ac[4+i] = As[(64 + ty*4 + i)*17 + kk + 2];
            }
            {
                float4 u0 = *(float4*)(Bs + (kk+2)*128 + tx*4);
                float4 u1 = *(float4*)(Bs + (kk+2)*128 + 64 + tx*4);
                bc[0]=u0.x; bc[1]=u0.y; bc[2]=u0.z; bc[3]=u0.w;
                bc[4]=u1.x; bc[5]=u1.y; bc[6]=u1.z; bc[7]=u1.w;
            }
            #pragma unroll
            for (int i = 0; i < 8; i++)
                #pragma unroll
                for (int j = 0; j < 8; j++)
                    acc[i][j] += an[i]*bn[j];
        }
        __syncthreads();
    }
    #pragma unroll
    for (int i = 0; i < 8; i++) {
        int row = m0 + ((i < 4) ? (ty*4 + i) : (64 + ty*4 + i - 4));
        float* cp = C + (long)row*N;
        int c0 = tx*4, c1 = 64 + tx*4;
        float4 o0 = make_float4(acc[i][0],acc[i][1],acc[i][2],acc[i][3]);
        float4 o1 = make_float4(acc[i][4],acc[i][5],acc[i][6],acc[i][7]);
        if (c0 < N) *(float4*)(cp + c0) = o0;
        if (c1 < N) *(float4*)(cp + c1) = o1;
    }
}

// ================= fused flash attention (pipelined) =================
__global__ __launch_bounds__(256)
void attn_kernel(const int* __restrict__ lengths) {
    extern __shared__ float sm[];
    float* Qs = sm;
    float* KVs = sm + 64*129;
    float* Ps = sm + 2*64*129;

    int b  = blockIdx.y;
    int qt = 3 - blockIdx.x;
    int q0 = qt * 64;
    int len = lengths[b];
    if (q0 >= len) return;

    int tid = threadIdx.x;
    int tx = tid & 15, ty = tid >> 4;
    const float scale = 0.08838834764831845f;

    const float* Qg = g_Q + (long)(b*cT + q0)*cE;
    #pragma unroll
    for (int i = 0; i < 8; i++) {
        int idx = tid + i*256;
        int r = idx >> 5, e4 = (idx & 31) << 2;
        float4 v = *(const float4*)(Qg + r*cE + e4);
        float* qs = Qs + r*129 + e4;
        qs[0]=v.x*scale; qs[1]=v.y*scale; qs[2]=v.z*scale; qs[3]=v.w*scale;
    }
    float O[4][8] = {};
    float mr[4], lr[4];
    #pragma unroll
    for (int i = 0; i < 4; i++) { mr[i] = -1e30f; lr[i] = 0.f; }
    __syncthreads();

    int ktmax = min(qt, ((len + 63) >> 6) - 1);
    for (int kt = 0; kt <= ktmax; kt++) {
        const float* Kg = g_K + (long)(b*cT + kt*64)*cE;
        #pragma unroll
        for (int i = 0; i < 8; i++) {
            int idx = tid + i*256;
            int r = idx >> 5, e4 = (idx & 31) << 2;
            float4 v = *(const float4*)(Kg + r*cE + e4);
            float* ks = KVs + r*129 + e4;
            ks[0]=v.x; ks[1]=v.y; ks[2]=v.z; ks[3]=v.w;
        }
        __syncthreads();
        float s[4][4] = {};
        float a0[4], b0[4];
        #pragma unroll
        for (int i = 0; i < 4; i++) {
            a0[i] = Qs[(ty*4 + i)*129];
            b0[i] = KVs[(tx*4 + i)*129];
        }
        #pragma unroll 4
        for (int kk = 0; kk < 128; kk += 2) {
            float a1[4], b1[4];
            #pragma unroll
            for (int i = 0; i < 4; i++) {
                a1[i] = Qs[(ty*4 + i)*129 + kk + 1];
                b1[i] = KVs[(tx*4 + i)*129 + kk + 1];
            }
            #pragma unroll
            for (int i = 0; i < 4; i++)
                #pragma unroll
                for (int j = 0; j < 4; j++)
                    s[i][j] += a0[i]*b0[j];
            #pragma unroll
            for (int i = 0; i < 4; i++) {
                a0[i] = Qs[(ty*4 + i)*129 + kk + 2];
                b0[i] = KVs[(tx*4 + i)*129 + kk + 2];
            }
            #pragma unroll
            for (int i = 0; i < 4; i++)
                #pragma unroll
                for (int j = 0; j < 4; j++)
                    s[i][j] += a1[i]*b1[j];
        }
        int kbase = kt*64;
        bool diag = (kt == qt);
        #pragma unroll
        for (int i = 0; i < 4; i++) {
            int q = q0 + ty*4 + i;
            #pragma unroll
            for (int j = 0; j < 4; j++) {
                int k = kbase + tx*4 + j;
                if ((diag && k > q) || k >= len) s[i][j] = -1e30f;
            }
        }
        #pragma unroll
        for (int i = 0; i < 4; i++) {
            float m2 = fmaxf(fmaxf(s[i][0], s[i][1]), fmaxf(s[i][2], s[i][3]));
            #pragma unroll
            for (int o = 1; o < 16; o <<= 1)
                m2 = fmaxf(m2, __shfl_xor_sync(0xffffffffu, m2, o));
            float mn = fmaxf(mr[i], m2);
            float al = __expf(mr[i] - mn);
            mr[i] = mn;
            float r = 0.f;
            #pragma unroll
            for (int j = 0; j < 4; j++) {
                float p = __expf(s[i][j] - mn);
                s[i][j] = p; r += p;
            }
            #pragma unroll
            for (int o = 1; o < 16; o <<= 1)
                r += __shfl_xor_sync(0xffffffffu, r, o);
            lr[i] = lr[i]*al + r;
            #pragma unroll
            for (int j = 0; j < 8; j++) O[i][j] *= al;
        }
        #pragma unroll
        for (int i = 0; i < 4; i++)
            #pragma unroll
            for (int j = 0; j < 4; j++)
                Ps[(ty*4 + i)*65 + tx*4 + j] = s[i][j];
        __syncthreads();
        const float* Vg = g_V + (long)(b*cT + kt*64)*cE;
        #pragma unroll
        for (int i = 0; i < 8; i++) {
            int idx = tid + i*256;
            int r = idx >> 5, e4 = (idx & 31) << 2;
            *(float4*)(KVs + r*128 + e4) = *(const float4*)(Vg + r*cE + e4);
        }
        __syncthreads();
        float p0[4];
        float4 u0, u1;
        #pragma unroll
        for (int i = 0; i < 4; i++) p0[i] = Ps[(ty*4 + i)*65];
        u0 = *(float4*)(KVs + tx*4);
        u1 = *(float4*)(KVs + 64 + tx*4);
        #pragma unroll 4
        for (int kk = 0; kk < 64; kk += 2) {
            float p1[4]; float4 w0, w1;
            #pragma unroll
            for (int i = 0; i < 4; i++) p1[i] = Ps[(ty*4 + i)*65 + kk + 1];
            w0 = *(float4*)(KVs + (kk+1)*128 + tx*4);
            w1 = *(float4*)(KVs + (kk+1)*128 + 64 + tx*4);
            #pragma unroll
            for (int i = 0; i < 4; i++) {
                O[i][0] += p0[i]*u0.x; O[i][1] += p0[i]*u0.y;
                O[i][2] += p0[i]*u0.z; O[i][3] += p0[i]*u0.w;
                O[i][4] += p0[i]*u1.x; O[i][5] += p0[i]*u1.y;
                O[i][6] += p0[i]*u1.z; O[i][7] += p0[i]*u1.w;
            }
            #pragma unroll
            for (int i = 0; i < 4; i++) p0[i] = Ps[(ty*4 + i)*65 + kk + 2];
            u0 = *(float4*)(KVs + (kk+2)*128 + tx*4);
            u1 = *(float4*)(KVs + (kk+2)*128 + 64 + tx*4);
            #pragma unroll
            for (int i = 0; i < 4; i++) {
                O[i][0] += p1[i]*w0.x; O[i][1] += p1[i]*w0.y;
                O[i][2] += p1[i]*w0.z; O[i][3] += p1[i]*w0.w;
                O[i][4] += p1[i]*w1.x; O[i][5] += p1[i]*w1.y;
                O[i][6] += p1[i]*w1.z; O[i][7] += p1[i]*w1.w;
            }
        }
        __syncthreads();
    }
    float* AHg = g_AH + (long)(b*cT + q0)*cE;
    #pragma unroll
    for (int i = 0; i < 4; i++) {
        float inv = 1.f / lr[i];
        float4 o0 = make_float4(O[i][0]*inv, O[i][1]*inv, O[i][2]*inv, O[i][3]*inv);
        float4 o1 = make_float4(O[i][4]*inv, O[i][5]*inv, O[i][6]*inv, O[i][7]*inv);
        float* op = AHg + (long)(ty*4 + i)*cE;
        *(float4*)(op + tx*4)      = o0;
        *(float4*)(op + 64 + tx*4) = o1;
    }
}

// ================= MLP as register-tiled tile-GEMM + NLL =================
// Block = (chunk cx, b): 16 t x 8 deg = 128 rows. K=100, N=50 (padded 64).
// Threads 256: tx=tid&15 (4 cols), ty=tid>>4 (8 rows).
__global__ __launch_bounds__(256)
void mlp_kernel(const int* __restrict__ xs, const int* __restrict__ lengths,
                const int* __restrict__ acts, const int* __restrict__ dest,
                const int* __restrict__ adj, const int* __restrict__ seg,
                const int* __restrict__ stp, const float* __restrict__ loc,
                const float* __restrict__ TD,
                const float* __restrict__ W2, const float* __restrict__ b2,
                const float* __restrict__ W3, const float* __restrict__ b3,
                const float* __restrict__ obb1, const float* __restrict__ obW2,
                const float* __restrict__ obb2) {
    extern __shared__ float sh[];
    float* Bs    = sh;                 // [102][64]
    float* As    = sh + 102*64;        // [128][102]
    float* sHc   = As + 128*102;       // [16][100]
    float* sDist = sHc + 16*100;       // [128]
    float* sUx   = sDist + 128;
    float* sUy   = sUx + 128;
    float* sOb   = sUy + 128;          // [128] ob-branch contribution
    float* sDbC  = sOb + 128;          // [100]
    float* sAd   = sDbC + 100;
    float* sAx   = sAd + 100;
    float* sAy   = sAx + 100;
    float* sW3   = sAy + 100;          // [64]
    float* sB2   = sW3 + 64;           // [64]
    float* sSm   = sB2 + 64;           // su1[25] sw1b[25] sobW2[25] sobb1[25]
    float* sLog  = sSm + 100;          // [128]
    float* sSt   = sLog + 128;         // [192]
    float* sMisc = sSt + 192;          // [4]: mean, inv, lb, nllsum

    int b = blockIdx.y;
    int len = lengths[b];
    int t0 = blockIdx.x * 16;
    int tid = threadIdx.x;
    if (t0 >= len - 1) {
        if (tid == 0) g_pparts[blockIdx.x*cB + b] = 0.f;
        return;
    }
    int tmax = min(t0 + 16, len - 1);

    // ---- phase A: loads ----
    for (int i = tid; i < 102*64; i += 256) {
        int k = i >> 6, n = i & 63;
        Bs[i] = (k < 100 && n < 50) ? W2[k*50 + n] : 0.f;
    }
    for (int i = tid; i < 16*100; i += 256)
        sHc[i] = g_Hc[((long)(b*cT + t0) + i/100)*cHID + i%100];
    if (tid < cHID) {
        sDbC[tid] = g_Db[b*cHID + tid] + g_Cv[tid];
        sAd[tid] = g_Ad[tid]; sAx[tid] = g_Ax[tid]; sAy[tid] = g_Ay[tid];
    }
    if (tid < 64) {
        sW3[tid] = (tid < 50) ? W3[tid] : 0.f;
        sB2[tid] = (tid < 50) ? b2[tid] : 0.f;
        sSt[tid]     = g_sparts[tid*3];
        sSt[64+tid]  = g_sparts[tid*3+1];
        sSt[128+tid] = g_sparts[tid*3+2];
    }
    if (tid < 25) {
        sSm[tid]    = g_u1[tid];  sSm[25+tid] = g_w1b[tid];
        sSm[50+tid] = obW2[tid];  sSm[75+tid] = obb1[tid];
    }
    if (tid == 0) sMisc[2] = b3[0] + obb2[0];
    __syncthreads();
    if (tid == 0) {
        float s = 0.f, ss = 0.f, c = 0.f;
        for (int i = 0; i < 64; i++) { s += sSt[i]; ss += sSt[64+i]; c += sSt[128+i]; }
        float mean = s / c;
        float var = (ss - c*mean*mean) / (c - 1.f);
        sMisc[0] = mean;
        sMisc[1] = 1.f / (sqrtf(var) + 1e-6f);
    }
    __syncthreads();

    // ---- phase B: per-row features + ob branch (128 threads) ----
    if (tid < 128) {
        int tl = tid >> 3, d = tid & 7;
        int t = t0 + tl;
        int x = xs[b*cT + t];
        int nb = adj[x*cDEG + d];
        int db_ = dest[b];
        float nx = loc[nb*2], ny = loc[nb*2 + 1];
        float dx = loc[db_*2], dy = loc[db_*2 + 1];
        float cx = loc[x*2],  cy = loc[x*2 + 1];
        float dist = (fabsf(nx - dx) + fabsf(ny - dy)) * 100.f;
        float vx = nx - cx, vy = ny - cy;
        float inv = 1.f / (sqrtf(vx*vx + vy*vy) + 1e-8f);
        sDist[tid] = dist;
        sUx[tid] = vx*inv;
        sUy[tid] = vy*inv;
        float mf = (nb != 0) ? 1.f : 0.f;
        float tt = TD[(long)seg[x*cDEG + d]*cNBUCKET + stp[0]];
        float ttw = (tt - sMisc[0]) * sMisc[1];
        float ob = 0.f;
        #pragma unroll
        for (int i = 0; i < 25; i++) {
            float z = mf*(ttw*sSm[i] + sSm[25+i]) + sSm[75+i];
            ob += fmaxf(z, 0.f) * sSm[50+i];
        }
        sOb[tid] = ob;
    }
    __syncthreads();

    // ---- phase C: h1 fill. As[row][k], stride 102 ----
    for (int i = tid; i < 128*100; i += 256) {
        int row = i & 127, k = i >> 7;
        int tl = row >> 3;
        float h = sHc[tl*100 + k] + sDbC[k] + sDist[row]*sAd[k]
                + sUx[row]*sAx[k] + sUy[row]*sAy[k];
        As[row*102 + k] = fmaxf(h, 0.f);
    }
    if (tid < 256) {
        int row = tid >> 1;
        As[row*102 + 100 + (tid & 1)] = 0.f;
    }
    __syncthreads();

    // ---- phase D: GEMM 128x64x100, acc[8][4], double-buffered ----
    int tx = tid & 15, ty = tid >> 4;
    float acc[8][4] = {};
    float ac[8]; float4 bc;
    #pragma unroll
    for (int i = 0; i < 8; i++) ac[i] = As[(ty*8 + i)*102];
    bc = *(float4*)(Bs + tx*4);
    #pragma unroll 2
    for (int kk = 0; kk < 100; kk += 2) {
        float an[8]; float4 bn;
        #pragma unroll
        for (int i = 0; i < 8; i++) an[i] = As[(ty*8 + i)*102 + kk + 1];
        bn = *(float4*)(Bs + (kk+1)*64 + tx*4);
        #pragma unroll
        for (int i = 0; i < 8; i++) {
            acc[i][0] += ac[i]*bc.x; acc[i][1] += ac[i]*bc.y;
            acc[i][2] += ac[i]*bc.z; acc[i][3] += ac[i]*bc.w;
        }
        #pragma unroll
        for (int i = 0; i < 8; i++) ac[i] = As[(ty*8 + i)*102 + kk + 2];  // k=100 zeros
        bc = *(float4*)(Bs + (kk+2)*64 + tx*4);                            // row 100 zeros
        #pragma unroll
        for (int i = 0; i < 8; i++) {
            acc[i][0] += an[i]*bn.x; acc[i][1] += an[i]*bn.y;
            acc[i][2] += an[i]*bn.z; acc[i][3] += an[i]*bn.w;
        }
    }

    // ---- epilogue: relu + W3 dot, half-warp reduce ----
    float w3v[4], b2v[4];
    #pragma unroll
    for (int j = 0; j < 4; j++) { w3v[j] = sW3[tx*4 + j]; b2v[j] = sB2[tx*4 + j]; }
    float lb = sMisc[2];
    #pragma unroll
    for (int i = 0; i < 8; i++) {
        float part = 0.f;
        #pragma unroll
        for (int j = 0; j < 4; j++)
            part += fmaxf(acc[i][j] + b2v[j], 0.f) * w3v[j];
        #pragma unroll
        for (int o = 8; o > 0; o >>= 1)
            part += __shfl_xor_sync(0xffffffffu, part, o);
        if (tx == 0) {
            int row = ty*8 + i;
            sLog[row] = part + sOb[row] + lb;
        }
    }
    __syncthreads();

    // ---- NLL per t, reduce over chunk ----
    if (tid < 16) {
        float nll = 0.f;
        int t = t0 + tid;
        if (t < tmax) {
            float l0[8];
            #pragma unroll
            for (int i = 0; i < 8; i++) l0[i] = sLog[tid*8 + i];
            float m = l0[0];
            #pragma unroll
            for (int i = 1; i < 8; i++) m = fmaxf(m, l0[i]);
            float s = 0.f;
            #pragma unroll
            for (int i = 0; i < 8; i++) s += __expf(l0[i] - m);
            int a = acts[b*cTM1 + t];
            nll = (m + __logf(s)) - l0[a];
        }
        #pragma unroll
        for (int o = 8; o > 0; o >>= 1)
            nll += __shfl_xor_sync(0xffffffffu, nll, o);
        if (tid == 0) g_pparts[blockIdx.x*cB + b] = nll;
    }
}

// ---------------- final reduce ----------------
__global__ void final_kernel(const int* __restrict__ lengths, float* __restrict__ out) {
    __shared__ float r[64];
    int t = threadIdx.x;
    float s = 0.f;
    #pragma unroll
    for (int c = 0; c < cCH; c++) s += g_pparts[c*cB + t];
    r[t] = s / (float)(lengths[t] - 1);
    __syncthreads();
    for (int o = 32; o > 0; o >>= 1) {
        if (t < o) r[t] += r[t + o];
        __syncthreads();
    }
    if (t == 0) out[0] = r[0];
}

// ---------------- launch ----------------
extern "C" void kernel_launch(void* const* d_in, const int* in_sizes, int n_in,
                              void* d_out, int out_size) {
    const int*   xs      = (const int*)  d_in[0];
    const int*   lengths = (const int*)  d_in[1];
    const int*   acts    = (const int*)  d_in[2];
    const int*   dest    = (const int*)  d_in[3];
    const int*   adj     = (const int*)  d_in[4];
    const int*   seg     = (const int*)  d_in[5];
    const int*   stp     = (const int*)  d_in[6];
    const float* loc     = (const float*)d_in[7];
    const float* TD      = (const float*)d_in[8];
    const float* emb     = (const float*)d_in[9];
    const float* Wq      = (const float*)d_in[10];
    const float* Wk      = (const float*)d_in[11];
    const float* Wv      = (const float*)d_in[12];
    const float* Wo      = (const float*)d_in[13];
    const float* distW   = (const float*)d_in[14];
    const float* distb   = (const float*)d_in[15];
    const float* dirW    = (const float*)d_in[16];
    const float* dirb    = (const float*)d_in[17];
    const float* ttW     = (const float*)d_in[18];
    const float* ttb     = (const float*)d_in[19];
    const float* obW1    = (const float*)d_in[20];
    const float* obb1    = (const float*)d_in[21];
    const float* obW2    = (const float*)d_in[22];
    const float* obb2    = (const float*)d_in[23];
    const float* W1      = (const float*)d_in[24];
    const float* omb1    = (const float*)d_in[25];
    const float* W2      = (const float*)d_in[26];
    const float* b2      = (const float*)d_in[27];
    const float* W3      = (const float*)d_in[28];
    const float* b3      = (const float*)d_in[29];

    float *pQ, *pK, *pV, *pAH, *pHc, *pWoW1;
    cudaGetSymbolAddress((void**)&pQ,  g_Q);
    cudaGetSymbolAddress((void**)&pK,  g_K);
    cudaGetSymbolAddress((void**)&pV,  g_V);
    cudaGetSymbolAddress((void**)&pAH, g_AH);
    cudaGetSymbolAddress((void**)&pHc, g_Hc);
    cudaGetSymbolAddress((void**)&pWoW1, g_WoW1);

    const int ASMEM = (2*64*129 + 64*65) * 4;
    cudaFuncSetAttribute(attn_kernel, cudaFuncAttributeMaxDynamicSharedMemorySize, ASMEM);
    const int MSMEM = (102*64 + 128*102 + 16*100 + 4*128 + 4*100 + 2*64 + 100
                       + 128 + 192 + 4) * 4;
    cudaFuncSetAttribute(mlp_kernel, cudaFuncAttributeMaxDynamicSharedMemorySize, MSMEM);

    setup_kernel<<<257, 128>>>(Wo, W1, dest, emb, distW, distb, dirW, dirb,
                               ttW, ttb, obW1, omb1,
                               xs, lengths, adj, seg, TD, stp);

    gemm128<<<dim3(3, 128), 256>>>(nullptr, xs, emb, Wq, Wk, Wv,
                                   pQ, pK, pV, lengths, cE, 1);

    attn_kernel<<<dim3(4, cB), 256, ASMEM>>>(lengths);

    gemm128<<<dim3(1, 128), 256>>>(pAH, nullptr, nullptr, pWoW1, nullptr, nullptr,
                                   pHc, nullptr, nullptr, lengths, cHID, 2);

    mlp_kernel<<<dim3(cCH, cB), 256, MSMEM>>>(xs, lengths, acts, dest, adj, seg, stp,
                                              loc, TD, W2, b2, W3, b3,
                                              obb1, obW2, obb2);

    final_kernel<<<1, 64>>>(lengths, (float*)d_out);
}